// round 6
// baseline (speedup 1.0000x reference)
#include <cuda_runtime.h>

// CPHASE on qubits (0,1) of a 22-qubit batched state (B=4).
// Qubits (0,1) are slowest axes => |11> subspace = last quarter of flat array.
// Batch (B=4) innermost => 4 consecutive floats = one amplitude's batch lanes.
//
// out[0 : 2^24]    = new re plane
// out[2^24 : 2^25] = new im plane
//
// R6: 256-bit loads/stores (ld/st.global.v8.f32, sm_100+). One thread moves
//     one float8 (2 amplitudes x 4 batch lanes) per plane. Same structure as
//     R1 otherwise (16384-block classic launch, which beat persistent grids).

#define N8      (1u << 21)         // float8 count per plane
#define THRESH8 (3u << 19)         // float8s below this: identity
#define TPB     256u

struct F8 { float v[8]; };

__device__ __forceinline__ F8 ldg256(const float* p) {
    F8 r;
    asm volatile("ld.global.v8.f32 {%0,%1,%2,%3,%4,%5,%6,%7}, [%8];"
        : "=f"(r.v[0]), "=f"(r.v[1]), "=f"(r.v[2]), "=f"(r.v[3]),
          "=f"(r.v[4]), "=f"(r.v[5]), "=f"(r.v[6]), "=f"(r.v[7])
        : "l"(p));
    return r;
}

__device__ __forceinline__ void stg256(float* p, const F8& r) {
    asm volatile("st.global.v8.f32 [%0], {%1,%2,%3,%4,%5,%6,%7,%8};"
        :: "l"(p),
           "f"(r.v[0]), "f"(r.v[1]), "f"(r.v[2]), "f"(r.v[3]),
           "f"(r.v[4]), "f"(r.v[5]), "f"(r.v[6]), "f"(r.v[7])
        : "memory");
}

__global__ __launch_bounds__(TPB) void cphase_kernel(
    const float* __restrict__ re,
    const float* __restrict__ im,
    const float* __restrict__ theta,
    float*       __restrict__ out)
{
    const unsigned i = blockIdx.x * TPB + threadIdx.x;   // float8 index
    const unsigned off = i * 8u;

    F8 r = ldg256(re + off);
    F8 m = ldg256(im + off);

    if (i >= THRESH8) {
        // |11> block: rotate each batch lane by theta[b]; pattern repeats x2.
        float c[4], s[4];
        __sincosf(theta[0], &s[0], &c[0]);
        __sincosf(theta[1], &s[1], &c[1]);
        __sincosf(theta[2], &s[2], &c[2]);
        __sincosf(theta[3], &s[3], &c[3]);

        #pragma unroll
        for (int k = 0; k < 8; k++) {
            const int b = k & 3;
            float nr = fmaf(r.v[k], c[b], -m.v[k] * s[b]);
            m.v[k]   = fmaf(r.v[k], s[b],  m.v[k] * c[b]);
            r.v[k]   = nr;
        }
    }

    stg256(out + off,            r);   // re plane
    stg256(out + off + 8u * N8,  m);   // im plane
}

extern "C" void kernel_launch(void* const* d_in, const int* in_sizes, int n_in,
                              void* d_out, int out_size)
{
    const float* re    = (const float*)d_in[0];
    const float* im    = (const float*)d_in[1];
    const float* theta = (const float*)d_in[2];
    float* out = (float*)d_out;

    cphase_kernel<<<N8 / TPB, TPB>>>(re, im, theta, out);
}

// round 7
// speedup vs baseline: 1.0021x; 1.0021x over previous
#include <cuda_runtime.h>

// CPHASE on qubits (0,1) of a 22-qubit batched state (B=4).  FINAL (= R1).
//
// state shape: (2,)*22 + (4,) -> flattened 2^22 * 4 = 2^24 floats each re/im.
// Qubits (0,1) are the slowest axes => |11> subspace is the LAST quarter of
// the flattened array. Batch is innermost => one float4 = 4 batch lanes, and
// the per-component rotation angles are theta[0..3] directly.
//
// out[0 : 2^24]    = new re plane
// out[2^24 : 2^25] = new im plane
//
// Verdict after 6 rounds: pure HBM-bound stream, 268 MB irreducible traffic,
// ~7.5 TB/s effective (~94% of spec). ILP, persistent grids, __ldcs/__stcs/
// __stwt, and 256-bit ld/st were all neutral or worse; this minimal classic
// launch is the measured floor (kernel 35.55us, bench 43.49us).

#define N4     (1u << 22)          // float4 count per plane
#define THRESH (3u << 20)          // first 3/4 of float4s: identity

__global__ __launch_bounds__(256) void cphase_kernel(
    const float4* __restrict__ re,
    const float4* __restrict__ im,
    const float*  __restrict__ theta,
    float4* __restrict__ out)
{
    unsigned i = blockIdx.x * blockDim.x + threadIdx.x;   // 0 .. N4-1
    float4 r = re[i];
    float4 m = im[i];

    float4 orr, omm;
    if (i >= THRESH) {
        // |11> block: rotate each batch lane by theta[b]
        float c0, s0, c1, s1, c2, s2, c3, s3;
        __sincosf(theta[0], &s0, &c0);
        __sincosf(theta[1], &s1, &c1);
        __sincosf(theta[2], &s2, &c2);
        __sincosf(theta[3], &s3, &c3);
        orr.x = fmaf(r.x, c0, -m.x * s0);  omm.x = fmaf(r.x, s0, m.x * c0);
        orr.y = fmaf(r.y, c1, -m.y * s1);  omm.y = fmaf(r.y, s1, m.y * c1);
        orr.z = fmaf(r.z, c2, -m.z * s2);  omm.z = fmaf(r.z, s2, m.z * c2);
        orr.w = fmaf(r.w, c3, -m.w * s3);  omm.w = fmaf(r.w, s3, m.w * c3);
    } else {
        orr = r;
        omm = m;
    }

    out[i]      = orr;       // re plane
    out[i + N4] = omm;       // im plane
}

extern "C" void kernel_launch(void* const* d_in, const int* in_sizes, int n_in,
                              void* d_out, int out_size)
{
    const float4* re    = (const float4*)d_in[0];
    const float4* im    = (const float4*)d_in[1];
    const float*  theta = (const float*)d_in[2];
    float4* out = (float4*)d_out;

    cphase_kernel<<<N4 / 256, 256>>>(re, im, theta, out);
}

// round 8
// speedup vs baseline: 1.0316x; 1.0294x over previous
#include <cuda_runtime.h>

// CPHASE on qubits (0,1) of a 22-qubit batched state (B=4).  FINAL (= R1).
//
// state shape: (2,)*22 + (4,) -> flattened 2^22 * 4 = 2^24 floats each re/im.
// Qubits (0,1) are the slowest axes => |11> subspace is the LAST quarter of
// the flattened array. Batch is innermost => one float4 = 4 batch lanes, and
// the per-component rotation angles are theta[0..3] directly.
//
// out[0 : 2^24]    = new re plane
// out[2^24 : 2^25] = new im plane
//
// Converged after 7 rounds: pure HBM-bound stream, 268 MB irreducible
// traffic, ~7.5 TB/s effective wallclock rate (~94% of 8 TB/s spec).
// Tested and rejected: ILP x2, persistent grid (regressed), __ldcs/__stcs/
// __stwt hints, 256-bit v8 ld/st, CE-memcpy hybrid (arithmetic), L2 policy
// windows (arithmetic). This minimal classic launch is the measured floor
// (kernel ~35.6us, bench ~43.5-44.8us).

#define N4     (1u << 22)          // float4 count per plane
#define THRESH (3u << 20)          // first 3/4 of float4s: identity

__global__ __launch_bounds__(256) void cphase_kernel(
    const float4* __restrict__ re,
    const float4* __restrict__ im,
    const float*  __restrict__ theta,
    float4* __restrict__ out)
{
    unsigned i = blockIdx.x * blockDim.x + threadIdx.x;   // 0 .. N4-1
    float4 r = re[i];
    float4 m = im[i];

    float4 orr, omm;
    if (i >= THRESH) {
        // |11> block: rotate each batch lane by theta[b]
        float c0, s0, c1, s1, c2, s2, c3, s3;
        __sincosf(theta[0], &s0, &c0);
        __sincosf(theta[1], &s1, &c1);
        __sincosf(theta[2], &s2, &c2);
        __sincosf(theta[3], &s3, &c3);
        orr.x = fmaf(r.x, c0, -m.x * s0);  omm.x = fmaf(r.x, s0, m.x * c0);
        orr.y = fmaf(r.y, c1, -m.y * s1);  omm.y = fmaf(r.y, s1, m.y * c1);
        orr.z = fmaf(r.z, c2, -m.z * s2);  omm.z = fmaf(r.z, s2, m.z * c2);
        orr.w = fmaf(r.w, c3, -m.w * s3);  omm.w = fmaf(r.w, s3, m.w * c3);
    } else {
        orr = r;
        omm = m;
    }

    out[i]      = orr;       // re plane
    out[i + N4] = omm;       // im plane
}

extern "C" void kernel_launch(void* const* d_in, const int* in_sizes, int n_in,
                              void* d_out, int out_size)
{
    const float4* re    = (const float4*)d_in[0];
    const float4* im    = (const float4*)d_in[1];
    const float*  theta = (const float*)d_in[2];
    float4* out = (float4*)d_out;

    cphase_kernel<<<N4 / 256, 256>>>(re, im, theta, out);
}